// round 1
// baseline (speedup 1.0000x reference)
#include <cuda_runtime.h>

// TropicalDense: out[b,o] = max_{s in {0,1}, d} ( (s==0 ? X[b,d] : -X[b,d]) + K[s,d,o] )
// B=1024, D=512, O=256, all float32.

#define B_DIM 1024
#define D_DIM 512
#define O_DIM 256

#define BM 64   // batch tile per block
#define BO 32   // output tile per block
#define DC 64   // d-chunk through shared memory
#define NTHREADS 256

// ---- packed f32x2 helpers (sm_100a Blackwell packed fp32 pipe) ----
__device__ __forceinline__ unsigned long long pk2(float lo, float hi) {
    unsigned long long d;
    asm("mov.b64 %0, {%1, %2};" : "=l"(d) : "f"(lo), "f"(hi));
    return d;
}

__device__ __forceinline__ void addx2(unsigned long long a, unsigned long long b,
                                      float& lo, float& hi) {
    unsigned long long d;
    asm("add.rn.f32x2 %0, %1, %2;" : "=l"(d) : "l"(a), "l"(b));
    asm("mov.b64 {%0, %1}, %2;" : "=f"(lo), "=f"(hi) : "l"(d));
}

__global__ void __launch_bounds__(NTHREADS, 1)
tropical_dense_kernel(const float* __restrict__ X,
                      const float* __restrict__ K,
                      float* __restrict__ out) {
    // Xs transposed: Xs[dd][bb] so compute reads are contiguous per d-step.
    __shared__ float  Xs[DC][BM];
    // Ks interleaved pairs: Ks[dd][oo] = (K[0][d][o], K[1][d][o]) -> one LDS.64 feeds addx2.
    __shared__ float2 Ks[DC][BO];

    const int tid = threadIdx.x;
    const int tb  = tid >> 4;   // 0..15 : batch group
    const int to  = tid & 15;   // 0..15 : output lane
    const int b0  = blockIdx.y * BM;
    const int o0  = blockIdx.x * BO;

    float acc[4][2];
    #pragma unroll
    for (int i = 0; i < 4; i++)
        #pragma unroll
        for (int j = 0; j < 2; j++)
            acc[i][j] = __int_as_float(0xff800000);  // -inf

    for (int dc = 0; dc < D_DIM; dc += DC) {
        // ---- load X tile [BM x DC] (float4-coalesced), store transposed ----
        #pragma unroll
        for (int k = 0; k < (BM * DC / 4) / NTHREADS; k++) {   // 4 iters
            int t   = tid + k * NTHREADS;       // 0..1023 float4 slots
            int col = t & 15;                   // which float4 along d
            int row = t >> 4;                   // which batch row
            float4 v = *reinterpret_cast<const float4*>(
                &X[(size_t)(b0 + row) * D_DIM + dc + col * 4]);
            Xs[col * 4 + 0][row] = v.x;
            Xs[col * 4 + 1][row] = v.y;
            Xs[col * 4 + 2][row] = v.z;
            Xs[col * 4 + 3][row] = v.w;
        }
        // ---- load K tile: interleave (k0,k1) pairs, coalesced across oo ----
        #pragma unroll
        for (int k = 0; k < (DC * BO) / NTHREADS; k++) {       // 8 iters
            int t  = tid + k * NTHREADS;        // 0..2047 pair slots
            int oo = t & 31;
            int dd = t >> 5;
            float a = K[(size_t)(dc + dd) * O_DIM + o0 + oo];
            float b = K[(size_t)D_DIM * O_DIM + (size_t)(dc + dd) * O_DIM + o0 + oo];
            Ks[dd][oo] = make_float2(a, b);
        }
        __syncthreads();

        // ---- compute: alu-pipe (FMNMX) bound inner loop ----
        #pragma unroll 4
        for (int dd = 0; dd < DC; dd++) {
            float4 xv = *reinterpret_cast<const float4*>(&Xs[dd][tb * 4]);
            unsigned long long xp[4];
            xp[0] = pk2(xv.x, -xv.x);
            xp[1] = pk2(xv.y, -xv.y);
            xp[2] = pk2(xv.z, -xv.z);
            xp[3] = pk2(xv.w, -xv.w);
            unsigned long long kp0 =
                *reinterpret_cast<const unsigned long long*>(&Ks[dd][to]);
            unsigned long long kp1 =
                *reinterpret_cast<const unsigned long long*>(&Ks[dd][to + 16]);
            #pragma unroll
            for (int i = 0; i < 4; i++) {
                float lo, hi;
                addx2(xp[i], kp0, lo, hi);                     // (x+k0, -x+k1)
                acc[i][0] = fmaxf(acc[i][0], fmaxf(lo, hi));   // max3 fusion target
                addx2(xp[i], kp1, lo, hi);
                acc[i][1] = fmaxf(acc[i][1], fmaxf(lo, hi));
            }
        }
        __syncthreads();
    }

    // ---- epilogue: write 4x2 outputs per thread ----
    #pragma unroll
    for (int i = 0; i < 4; i++)
        #pragma unroll
        for (int j = 0; j < 2; j++)
            out[(size_t)(b0 + tb * 4 + i) * O_DIM + o0 + to + 16 * j] = acc[i][j];
}

extern "C" void kernel_launch(void* const* d_in, const int* in_sizes, int n_in,
                              void* d_out, int out_size) {
    const float* X = (const float*)d_in[0];   // [1024, 512]
    const float* K = (const float*)d_in[1];   // [2, 512, 256]
    float* out     = (float*)d_out;           // [1024, 256]

    dim3 grid(O_DIM / BO, B_DIM / BM);        // (8, 16) = 128 blocks
    tropical_dense_kernel<<<grid, NTHREADS>>>(X, K, out);
}